// round 17
// baseline (speedup 1.0000x reference)
#include <cuda_runtime.h>
#include <cstdint>

#define D      16
#define LIB    969
#define TPB    128
#define TILE_M 128
#define NKS8   128         // k8 steps over padded K (1024/8)

// Precomputed B fragments: masked coefficients as single tf32, laid out as
// mma.m16n8k8 col-major B fragments, both n-blocks packed:
// [k8step][lane] -> uint4 = { C[k0][n], C[k0+4][n], C[k0][n+8], C[k0+4][n+8] }
// with n = lane>>2, k0 = 8*kstep + (lane&3).
__device__ uint4 g_bfrag[NKS8 * 32];

// ---------------- helpers ----------------
__device__ __forceinline__ uint32_t smem_u32(const void* p) {
    uint32_t a;
    asm("{ .reg .u64 t; cvta.to.shared.u64 t, %1; cvt.u32.u64 %0, t; }"
        : "=r"(a) : "l"(p));
    return a;
}
#define LDSM4(r0, r1, r2, r3, addr)                                         \
    asm volatile("ldmatrix.sync.aligned.m8n8.x4.shared.b16 {%0,%1,%2,%3}, [%4];" \
                 : "=r"(r0), "=r"(r1), "=r"(r2), "=r"(r3) : "r"(addr))
// m16n8k8 tf32 MMA (A row-major from "ldmatrix-as-4xtf32-rows" trick)
#define MMA8(d, a0, a1, a2, a3, b0, b1)                                     \
    asm volatile("mma.sync.aligned.m16n8k8.row.col.f32.tf32.tf32.f32 "      \
                 "{%0,%1,%2,%3}, {%4,%5,%6,%7}, {%8,%9}, {%0,%1,%2,%3};"    \
                 : "+f"((d)[0]), "+f"((d)[1]), "+f"((d)[2]), "+f"((d)[3])   \
                 : "r"(a0), "r"(a1), "r"(a2), "r"(a3), "r"(b0), "r"(b1))

// ---------------- prep: mask + tf32(RN) -> B fragments ----------------
__global__ void prep_kernel(const float* __restrict__ coeff,
                            const float* __restrict__ fixedv,
                            const unsigned char* __restrict__ fmask)
{
    int id = blockIdx.x * blockDim.x + threadIdx.x;
    if (id >= NKS8 * 32) return;           // (kstep, lane)
    int ks   = id >> 5;
    int lane = id & 31;
    int n  = lane >> 2;
    int k0 = ks * 8 + (lane & 3);
    uint32_t v[4];
#pragma unroll
    for (int e = 0; e < 4; e++) {
        int k = k0 + (e & 1) * 4;
        int nn = n + (e >> 1) * 8;
        float c = 0.f;
        if (k < LIB) { int s = k * D + nn; c = fmask[s] ? fixedv[s] : coeff[s]; }
        asm("cvt.rna.tf32.f32 %0, %1;" : "=r"(v[e]) : "f"(c));
    }
    g_bfrag[id] = make_uint4(v[0], v[1], v[2], v[3]);
}

// ---------------- per-chunk MMA ----------------
// Theta tile: 128 rows x 64 tf32, row stride 256B, 16B-granule swizzle
// g' = g ^ (row & 7)  (store and load sides identical).
// ldmatrix x4: lanes 0-15 rows r..r+15 at granule 2ks, lanes 16-31 same rows
// at granule 2ks+1 -> a0..a3 are exactly the m16n8k8 tf32 A fragment.
__device__ __forceinline__ void chunk_mma(int c, int nks, uint32_t sT,
                                          float (&acc)[2][2][4], int lane, int w)
{
    __syncwarp();
#pragma unroll
    for (int ks = 0; ks < 8; ks++) {
        if (ks >= nks) break;
        uint4 b = __ldg(&g_bfrag[(c * 8 + ks) * 32 + lane]);
#pragma unroll
        for (int ms = 0; ms < 2; ms++) {
            int rl   = w * 32 + ms * 16 + (lane & 15);
            int slot = 2 * ks + (lane >> 4);
            uint32_t off = (uint32_t)(rl * 256)
                         + (uint32_t)((slot ^ (rl & 7)) << 4);
            uint32_t a0, a1, a2, a3;
            LDSM4(a0, a1, a2, a3, sT + off);
            MMA8(acc[ms][0], a0, a1, a2, a3, b.x, b.y);   // n 0..7
            MMA8(acc[ms][1], a0, a1, a2, a3, b.z, b.w);   // n 8..15
        }
    }
}

// ---------------- main kernel (R15 skeleton, tf32 single tile) ----------------
__global__ __launch_bounds__(TPB, 3) void sindy_kernel(
    const float* __restrict__ z,
    float* __restrict__ out,
    int B)
{
    __shared__ __align__(128) unsigned char sTheta[TILE_M * 256];  // 32 KB tf32 tile
    const uint32_t sT = smem_u32(sTheta);

    const int tid  = threadIdx.x;
    const int lane = tid & 31;
    const int w    = tid >> 5;
    const uint32_t rowoff = (uint32_t)tid * 256;
    const int swz = tid & 7;

    const long row_g = (long)blockIdx.x * TILE_M + tid;
    const bool valid = row_g < B;

    float zv[D];
    {
        const float4* p = (const float4*)(z + row_g * D);
#pragma unroll
        for (int q = 0; q < 4; q++) {
            float4 t4 = valid ? p[q] : make_float4(0.f, 0.f, 0.f, 0.f);
            zv[4*q+0] = t4.x; zv[4*q+1] = t4.y; zv[4*q+2] = t4.z; zv[4*q+3] = t4.w;
        }
    }

    float acc[2][2][4];
#pragma unroll
    for (int a = 0; a < 2; a++)
#pragma unroll
        for (int b = 0; b < 2; b++)
#pragma unroll
            for (int e = 0; e < 4; e++) acc[a][b][e] = 0.f;

    uint32_t buf[4];
    int t = 0;   // compile-time folded (everything below fully unrolled)

#define EMIT(expr) do {                                                          \
        float m_ = (expr);                                                       \
        uint32_t v_;                                                             \
        asm("cvt.rna.tf32.f32 %0, %1;" : "=r"(v_) : "f"(m_));                    \
        buf[t & 3] = v_;                                                         \
        if ((t & 3) == 3) {                                                      \
            int s_ = (t >> 2) & 15;                                              \
            uint32_t off_ = rowoff + (uint32_t)((s_ ^ swz) << 4);                \
            asm volatile("st.shared.v4.b32 [%0], {%1,%2,%3,%4};"                 \
                :: "r"(sT + off_), "r"(buf[0]), "r"(buf[1]),                     \
                   "r"(buf[2]), "r"(buf[3]) : "memory");                         \
        }                                                                        \
        if ((t & 63) == 63 && t < 960)                                           \
            chunk_mma(t >> 6, 8, sT, acc, lane, w);                              \
        t++;                                                                     \
    } while (0)

    EMIT(1.0f);                                      // constant term
#pragma unroll
    for (int i = 0; i < D; i++) EMIT(zv[i]);         // order 1
#pragma unroll
    for (int i = 0; i < D; i++)                      // order 2 (i<=j)
#pragma unroll
        for (int j = i; j < D; j++) EMIT(zv[i] * zv[j]);
#pragma unroll
    for (int i = 0; i < D; i++)                      // order 3 (i<=j<=k)
#pragma unroll
        for (int j = i; j < D; j++) {
            float pp = zv[i] * zv[j];
#pragma unroll
            for (int k = j; k < D; k++) EMIT(pp * zv[k]);
        }
    // Pad to 976 so the final chunk's two k8-steps (k 960..975) have their
    // theta slots stored; k>=976 is zero on both sides and skipped.
#pragma unroll
    for (int pad = LIB; pad < 976; pad++) EMIT(0.0f);
#undef EMIT
    chunk_mma(15, 2, sT, acc, lane, w);              // final chunk, 2 k8-steps

    // Epilogue: D fragments -> out (m16n8 accumulator layout, unchanged)
    const int g = lane >> 2, tig = lane & 3;
    const long rbase = (long)blockIdx.x * TILE_M + w * 32;
#pragma unroll
    for (int ms = 0; ms < 2; ms++)
#pragma unroll
        for (int nb = 0; nb < 2; nb++) {
            long r0 = rbase + ms * 16 + g;
            long r1 = r0 + 8;
            int  cn = nb * 8 + 2 * tig;
            if (r0 < B)
                *(float2*)(out + r0 * D + cn) =
                    make_float2(acc[ms][nb][0], acc[ms][nb][1]);
            if (r1 < B)
                *(float2*)(out + r1 * D + cn) =
                    make_float2(acc[ms][nb][2], acc[ms][nb][3]);
        }
}

extern "C" void kernel_launch(void* const* d_in, const int* in_sizes, int n_in,
                              void* d_out, int out_size)
{
    const float*         zin    = (const float*)d_in[0];
    const float*         coeff  = (const float*)d_in[1];
    const float*         fixedv = (const float*)d_in[2];
    const unsigned char* fmask  = (const unsigned char*)d_in[3];
    float*               out    = (float*)d_out;

    const int B = in_sizes[0] / D;

    prep_kernel<<<(NKS8 * 32 + 255) / 256, 256>>>(coeff, fixedv, fmask);

    const int grid = (B + TILE_M - 1) / TILE_M;
    sindy_kernel<<<grid, TPB>>>(zin, out, B);
}